// round 1
// baseline (speedup 1.0000x reference)
#include <cuda_runtime.h>

// CBOW negative-sampling loss.
// Shapes fixed by the problem: VOCAB=200000, D=128, C=8, K=5, B derived from in_sizes.
#define DIMS   128   // D
#define CCTX   8     // context_size
#define KNEG   5     // negatives per context slot
#define CK     40    // CCTX * KNEG
#define F4     32    // DIMS/4 float4 per row == warp lanes

// fixed scratch (allocation-free rule): one partial per block, grid = B/8 = 4096
__device__ float g_partials[8192];

__device__ __forceinline__ float warp_sum(float v) {
#pragma unroll
    for (int o = 16; o; o >>= 1) v += __shfl_xor_sync(0xffffffffu, v, o);
    return v;
}

__global__ __launch_bounds__(256) void cbow_loss_kernel(
    const float* __restrict__ u_weights,
    const float* __restrict__ v_weights,
    const int*   __restrict__ pos_u,
    const int*   __restrict__ pos_v,
    const int*   __restrict__ neg_v,
    int B)
{
    const int warp = threadIdx.x >> 5;
    const int lane = threadIdx.x & 31;
    const int b = blockIdx.x * 8 + warp;

    float loss = 0.0f;
    if (b < B) {
        const float4* __restrict__ vw4 = (const float4*)v_weights;
        const float4* __restrict__ uw4 = (const float4*)u_weights;

        // ---- V = sum of 8 context rows (each lane owns 4 dims) ----
        float4 V = make_float4(0.f, 0.f, 0.f, 0.f);
#pragma unroll
        for (int c = 0; c < CCTX; c++) {
            int r = __ldg(&pos_v[b * CCTX + c]);
            float4 x = __ldg(&vw4[(long)r * F4 + lane]);
            V.x += x.x; V.y += x.y; V.z += x.z; V.w += x.w;
        }

        // ---- positive score ----
        int ur = __ldg(&pos_u[b * CCTX]);
        float4 u4 = __ldg(&uw4[(long)ur * F4 + lane]);
        float pd = u4.x * V.x + u4.y * V.y + u4.z * V.z + u4.w * V.w;
        pd = warp_sum(pd);
        float ps = fminf(fmaxf(pd, -10.f), 10.f);
        loss = log1pf(__expf(-ps));   // -log_sigmoid(ps)

        // ---- negatives: preload all 40 indices into 2 regs/lane ----
        int idxA = __ldg(&neg_v[b * CK + lane]);                       // n in [0,32)
        int idxB = (lane < CK - 32) ? __ldg(&neg_v[b * CK + 32 + lane]) : 0;

        float nl = 0.0f;
#pragma unroll
        for (int n = 0; n < CK; n++) {
            int r = (n < 32) ? __shfl_sync(0xffffffffu, idxA, n)
                             : __shfl_sync(0xffffffffu, idxB, n - 32);
            float4 x = __ldg(&vw4[(long)r * F4 + lane]);
            float d = x.x * V.x + x.y * V.y + x.z * V.z + x.w * V.w;
            d = warp_sum(d);
            float s = fminf(fmaxf(d, -10.f), 10.f);
            nl += log1pf(__expf(s));   // -log_sigmoid(-s)
        }
        loss += nl * (1.0f / CK);
    }

    // block reduce (deterministic): lane0 of each warp -> shared -> thread 0
    __shared__ float sh[8];
    if (lane == 0) sh[warp] = loss;
    __syncthreads();
    if (threadIdx.x == 0) {
        float s = 0.f;
#pragma unroll
        for (int w = 0; w < 8; w++) s += sh[w];
        g_partials[blockIdx.x] = s;
    }
}

__global__ void cbow_reduce_kernel(float* __restrict__ out, int nparts, float inv_B)
{
    __shared__ float sh[256];
    float s = 0.f;
    for (int i = threadIdx.x; i < nparts; i += 256) s += g_partials[i];
    sh[threadIdx.x] = s;
    __syncthreads();
#pragma unroll
    for (int o = 128; o; o >>= 1) {
        if (threadIdx.x < o) sh[threadIdx.x] += sh[threadIdx.x + o];
        __syncthreads();
    }
    if (threadIdx.x == 0) out[0] = sh[0] * inv_B;
}

extern "C" void kernel_launch(void* const* d_in, const int* in_sizes, int n_in,
                              void* d_out, int out_size)
{
    const float* uw = (const float*)d_in[0];
    const float* vw = (const float*)d_in[1];
    const int*   pu = (const int*)d_in[2];
    const int*   pv = (const int*)d_in[3];
    const int*   nv = (const int*)d_in[4];

    int BC = in_sizes[2];        // B * C
    int B  = BC / CCTX;          // 32768
    int nblocks = (B + 7) / 8;   // 4096, one warp per batch element

    cbow_loss_kernel<<<nblocks, 256>>>(uw, vw, pu, pv, nv, B);
    cbow_reduce_kernel<<<1, 256>>>((float*)d_out, nblocks, 1.0f / (float)B);
}

// round 2
// speedup vs baseline: 1.3615x; 1.3615x over previous
#include <cuda_runtime.h>

// CBOW negative-sampling loss. VOCAB=200000, D=128, C=8, K=5, B from in_sizes.
#define DIMS   128
#define CCTX   8
#define KNEG   5
#define CK     40   // CCTX*KNEG
#define F4     32   // DIMS/4 float4 per row == warp lanes

// fixed scratch (allocation-free rule)
__device__ float        g_partials[4096];
__device__ unsigned int g_count = 0;

__device__ __forceinline__ float warp_sum(float v) {
#pragma unroll
    for (int o = 16; o; o >>= 1) v += __shfl_xor_sync(0xffffffffu, v, o);
    return v;
}

__global__ __launch_bounds__(256) void cbow_loss_kernel(
    const float* __restrict__ u_weights,
    const float* __restrict__ v_weights,
    const int*   __restrict__ pos_u,
    const int*   __restrict__ pos_v,
    const int*   __restrict__ neg_v,
    float*       __restrict__ out,
    int B, float inv_B)
{
    const int warp = threadIdx.x >> 5;
    const int lane = threadIdx.x & 31;
    const int b = blockIdx.x * 8 + warp;

    float loss = 0.0f;
    if (b < B) {
        const float4* __restrict__ vw4 = (const float4*)v_weights;
        const float4* __restrict__ uw4 = (const float4*)u_weights;

        // ---- V = sum of 8 context rows (lane owns 4 dims) ----
        float4 V = make_float4(0.f, 0.f, 0.f, 0.f);
#pragma unroll
        for (int c = 0; c < CCTX; c++) {
            int r = __ldg(&pos_v[b * CCTX + c]);
            float4 x = __ldg(&vw4[(long)r * F4 + lane]);
            V.x += x.x; V.y += x.y; V.z += x.z; V.w += x.w;
        }

        // ---- positive score ----
        int ur = __ldg(&pos_u[b * CCTX]);
        float4 u4 = __ldg(&uw4[(long)ur * F4 + lane]);
        float pd = u4.x * V.x + u4.y * V.y + u4.z * V.z + u4.w * V.w;
        pd = warp_sum(pd);
        float ps = fminf(fmaxf(pd, -10.f), 10.f);
        loss = __logf(1.0f + __expf(-ps));   // -log_sigmoid(ps), fast softplus

        // ---- negatives: preload all 40 indices into 2 regs/lane ----
        int idxA = __ldg(&neg_v[b * CK + lane]);
        int idxB = (lane < CK - 32) ? __ldg(&neg_v[b * CK + 32 + lane]) : 0;

        // grouped softplus: prod of (1+e^s) over 8 terms, one __logf per group.
        // s clipped to [-10,10] -> term <= 22027, prod_8 <= 5.6e34 < FLT_MAX.
        float nl = 0.0f;
        float prod = 1.0f;
#pragma unroll
        for (int n = 0; n < CK; n++) {
            int r = (n < 32) ? __shfl_sync(0xffffffffu, idxA, n)
                             : __shfl_sync(0xffffffffu, idxB, n - 32);
            float4 x = __ldg(&vw4[(long)r * F4 + lane]);
            float d = x.x * V.x + x.y * V.y + x.z * V.z + x.w * V.w;
            d = warp_sum(d);
            float s = fminf(fmaxf(d, -10.f), 10.f);
            prod *= (1.0f + __expf(s));      // accumulate -log_sigmoid(-s) terms
            if ((n & 7) == 7) { nl += __logf(prod); prod = 1.0f; }
        }
        loss += nl * (1.0f / CK);
    }

    // ---- block reduce (deterministic order) ----
    __shared__ float shw[8];
    __shared__ float sh2[256];
    __shared__ bool  is_last;
    if (lane == 0) shw[warp] = loss;
    __syncthreads();

    if (threadIdx.x == 0) {
        float s = 0.f;
#pragma unroll
        for (int w = 0; w < 8; w++) s += shw[w];
        g_partials[blockIdx.x] = s;
        __threadfence();
        unsigned prev = atomicAdd(&g_count, 1u);
        is_last = (prev == gridDim.x - 1);
    }
    __syncthreads();

    // ---- last block folds all partials (deterministic fixed-tree) ----
    if (is_last) {
        float t = 0.f;
        for (int i = threadIdx.x; i < (int)gridDim.x; i += 256)
            t += __ldcg(&g_partials[i]);   // bypass L1: other SMs wrote these
        sh2[threadIdx.x] = t;
        __syncthreads();
#pragma unroll
        for (int o = 128; o; o >>= 1) {
            if (threadIdx.x < o) sh2[threadIdx.x] += sh2[threadIdx.x + o];
            __syncthreads();
        }
        if (threadIdx.x == 0) {
            out[0] = sh2[0] * inv_B;
            g_count = 0;                   // reset for next graph replay
        }
    }
}

extern "C" void kernel_launch(void* const* d_in, const int* in_sizes, int n_in,
                              void* d_out, int out_size)
{
    const float* uw = (const float*)d_in[0];
    const float* vw = (const float*)d_in[1];
    const int*   pu = (const int*)d_in[2];
    const int*   pv = (const int*)d_in[3];
    const int*   nv = (const int*)d_in[4];

    int BC = in_sizes[2];        // B * C
    int B  = BC / CCTX;          // 32768
    int nblocks = (B + 7) / 8;   // 4096

    cbow_loss_kernel<<<nblocks, 256>>>(uw, vw, pu, pv, nv,
                                       (float*)d_out, B, 1.0f / (float)B);
}

// round 3
// speedup vs baseline: 1.4031x; 1.0305x over previous
#include <cuda_runtime.h>

// CBOW negative-sampling loss. VOCAB=200000, D=128, C=8, K=5.
#define CCTX   8
#define CK     40   // CCTX*KNEG
#define F4     32   // D/4 float4 per row == warp lanes

__device__ float        g_partials[4096];
__device__ unsigned int g_count = 0;

__device__ __forceinline__ float warp_sum(float v) {
#pragma unroll
    for (int o = 16; o; o >>= 1) v += __shfl_xor_sync(0xffffffffu, v, o);
    return v;
}

__device__ __forceinline__ float dot4(float4 a, float4 b) {
    return a.x * b.x + a.y * b.y + a.z * b.z + a.w * b.w;
}

// Reduce N per-lane partial dot values (N = 16 or 8) across the warp with a
// halving butterfly. On return each lane holds ONE fully-summed dot value,
// with each dot duplicated in (32/N) lanes. Returns per-lane weighted
// softplus contribution: (N/32) * log(1 + exp(clip(d))).
template<int N>
__device__ __forceinline__ float neg_group(
    const float4* __restrict__ vw4, float4 V,
    int idxA, int idxB, int n0, int lane)
{
    float d[N];
#pragma unroll
    for (int i = 0; i < N; i++) {
        int n = n0 + i;
        int r = (n < 32) ? __shfl_sync(0xffffffffu, idxA, n)
                         : __shfl_sync(0xffffffffu, idxB, n - 32);
        float4 x = __ldg(&vw4[(long)r * F4 + lane]);
        d[i] = dot4(x, V);
    }
    // halving butterfly: n values -> n/2 per stage
#pragma unroll
    for (int o = 16, n = N; n > 1; o >>= 1, n >>= 1) {
        int h = n >> 1;
#pragma unroll
        for (int i = 0; i < h; i++) {
            bool hi = (lane & o) != 0;
            float send = hi ? d[i] : d[i + h];
            float recv = __shfl_xor_sync(0xffffffffu, send, o);
            d[i] = (hi ? d[i + h] : d[i]) + recv;
        }
    }
    // finish remaining lane-halving offsets so d[0] is the FULL 32-lane sum
#pragma unroll
    for (int o = (32 / N) >> 1; o; o >>= 1)
        d[0] += __shfl_xor_sync(0xffffffffu, d[0], o);

    float s = fminf(fmaxf(d[0], -10.f), 10.f);
    return __logf(1.0f + __expf(s)) * ((float)N / 32.0f);
}

__global__ __launch_bounds__(256) void cbow_loss_kernel(
    const float* __restrict__ u_weights,
    const float* __restrict__ v_weights,
    const int*   __restrict__ pos_u,
    const int*   __restrict__ pos_v,
    const int*   __restrict__ neg_v,
    float*       __restrict__ out,
    int B, float inv_B)
{
    const int warp = threadIdx.x >> 5;
    const int lane = threadIdx.x & 31;
    const int b = blockIdx.x * 8 + warp;

    float loss = 0.0f;
    if (b < B) {
        const float4* __restrict__ vw4 = (const float4*)v_weights;
        const float4* __restrict__ uw4 = (const float4*)u_weights;

        // ---- V = sum of 8 context rows (lane owns 4 dims) ----
        float4 V = make_float4(0.f, 0.f, 0.f, 0.f);
#pragma unroll
        for (int c = 0; c < CCTX; c++) {
            int r = __ldg(&pos_v[b * CCTX + c]);
            float4 x = __ldg(&vw4[(long)r * F4 + lane]);
            V.x += x.x; V.y += x.y; V.z += x.z; V.w += x.w;
        }

        // ---- positive score ----
        int ur = __ldg(&pos_u[b * CCTX]);
        float4 u4 = __ldg(&uw4[(long)ur * F4 + lane]);
        float pd = warp_sum(dot4(u4, V));
        float ps = fminf(fmaxf(pd, -10.f), 10.f);
        loss = __logf(1.0f + __expf(-ps));   // -log_sigmoid(ps)

        // ---- negatives: 40 indices preloaded into 2 regs/lane ----
        int idxA = __ldg(&neg_v[b * CK + lane]);
        int idxB = (lane < CK - 32) ? __ldg(&neg_v[b * CK + 32 + lane]) : 0;

        float contrib = neg_group<16>(vw4, V, idxA, idxB,  0, lane)
                      + neg_group<16>(vw4, V, idxA, idxB, 16, lane)
                      + neg_group< 8>(vw4, V, idxA, idxB, 32, lane);
        // warp_sum(contrib) = sum over all 40 dots of softplus (dups weighted out)
        loss += warp_sum(contrib) * (1.0f / CK);
    }

    // ---- block reduce (deterministic order) ----
    __shared__ float shw[8];
    __shared__ float sh2[256];
    __shared__ bool  is_last;
    if (lane == 0) shw[warp] = loss;
    __syncthreads();

    if (threadIdx.x == 0) {
        float s = 0.f;
#pragma unroll
        for (int w = 0; w < 8; w++) s += shw[w];
        g_partials[blockIdx.x] = s;
        __threadfence();
        unsigned prev = atomicAdd(&g_count, 1u);
        is_last = (prev == gridDim.x - 1);
    }
    __syncthreads();

    // ---- last block folds all partials (deterministic fixed-tree) ----
    if (is_last) {
        float t = 0.f;
        for (int i = threadIdx.x; i < (int)gridDim.x; i += 256)
            t += __ldcg(&g_partials[i]);
        sh2[threadIdx.x] = t;
        __syncthreads();
#pragma unroll
        for (int o = 128; o; o >>= 1) {
            if (threadIdx.x < o) sh2[threadIdx.x] += sh2[threadIdx.x + o];
            __syncthreads();
        }
        if (threadIdx.x == 0) {
            out[0] = sh2[0] * inv_B;
            g_count = 0;   // reset for next graph replay
        }
    }
}

extern "C" void kernel_launch(void* const* d_in, const int* in_sizes, int n_in,
                              void* d_out, int out_size)
{
    const float* uw = (const float*)d_in[0];
    const float* vw = (const float*)d_in[1];
    const int*   pu = (const int*)d_in[2];
    const int*   pv = (const int*)d_in[3];
    const int*   nv = (const int*)d_in[4];

    int BC = in_sizes[2];        // B * C
    int B  = BC / CCTX;          // 32768
    int nblocks = (B + 7) / 8;   // 4096

    cbow_loss_kernel<<<nblocks, 256>>>(uw, vw, pu, pv, nv,
                                       (float*)d_out, B, 1.0f / (float)B);
}